// round 16
// baseline (speedup 1.0000x reference)
#include <cuda_runtime.h>
#include <cuda_bf16.h>

#define BS 131072
#define PLEN 10
#define NCH1 23   // GEMM1: K=361 padded to 368 = 23 chunks of 16

// -------- pre-split weights: packed bf16 (2 per u32 along k), hi & lo, natural order.
// g_Whh holds 208 rows: 0-191 = Whh rows PERMUTED gate-interleaved per 48-row warp
// slice ([r x16 | z x16 | n x16] of the same 16 units), 192-193 = Wo, 194-207 = zero.
__device__ __align__(16) unsigned g_W1h[NCH1 * 256 * 8], g_W1l[NCH1 * 256 * 8]; // [kc][n][8]
__device__ __align__(16) unsigned g_W2h[4 * 128 * 32],   g_W2l[4 * 128 * 32];   // [kc][n][32]
__device__ __align__(16) unsigned g_W3h[64 * 64],        g_W3l[64 * 64];        // [n][64]
__device__ __align__(16) unsigned g_Whh[208 * 32],       g_Whl[208 * 32];       // [n][32]

// ---------------------------------------------------------------------------
__device__ __forceinline__ unsigned packbf(float lo, float hi) {
    unsigned r;
    asm("cvt.rn.bf16x2.f32 %0, %1, %2;" : "=r"(r) : "f"(hi), "f"(lo));
    return r;
}
__device__ __forceinline__ void split2(float v0, float v1, unsigned& hi, unsigned& lo) {
    hi = packbf(v0, v1);
    float h0 = __uint_as_float(hi << 16);
    float h1 = __uint_as_float(hi & 0xffff0000u);
    lo = packbf(v0 - h0, v1 - h1);
}
__device__ __forceinline__ float bflo(unsigned u) { return __uint_as_float(u << 16); }
__device__ __forceinline__ float bfhi(unsigned u) { return __uint_as_float(u & 0xffff0000u); }
__device__ __forceinline__ float relu_(float v) { return v > 0.f ? v : 0.f; }
__device__ __forceinline__ float tanhapx(float x) {
    float y; asm("tanh.approx.f32 %0, %1;" : "=f"(y) : "f"(x)); return y;
}

__device__ __forceinline__ void mma16(float* c, const unsigned* a, unsigned b0, unsigned b1) {
    asm("mma.sync.aligned.m16n8k16.row.col.f32.bf16.bf16.f32 "
        "{%0,%1,%2,%3},{%4,%5,%6,%7},{%8,%9},{%0,%1,%2,%3};"
        : "+f"(c[0]), "+f"(c[1]), "+f"(c[2]), "+f"(c[3])
        : "r"(a[0]), "r"(a[1]), "r"(a[2]), "r"(a[3]), "r"(b0), "r"(b1));
}

__device__ __forceinline__ void ldsm4(unsigned& r0, unsigned& r1, unsigned& r2, unsigned& r3,
                                      unsigned addr) {
    asm volatile("ldmatrix.sync.aligned.m8n8.x4.shared.b16 {%0,%1,%2,%3}, [%4];"
        : "=r"(r0), "=r"(r1), "=r"(r2), "=r"(r3) : "r"(addr));
}

__device__ __forceinline__ void cpa16(void* s, const void* g) {
    unsigned a = (unsigned)__cvta_generic_to_shared(s);
    asm volatile("cp.async.cg.shared.global [%0],[%1],16;" :: "r"(a), "l"(g) : "memory");
}
__device__ __forceinline__ void cp_commit() { asm volatile("cp.async.commit_group;" ::: "memory"); }
template <int N>
__device__ __forceinline__ void cp_wait() { asm volatile("cp.async.wait_group %0;" :: "n"(N) : "memory"); }

// 12-mma group, dependency distance 4; per-acc order (hh, hl, lh) preserved
#define MMA12(A0h, A1h, A0l, A1l, BH, BL, C0, C1)          \
    do {                                                    \
        mma16(C0, A0h, BH[0], BH[1]);                       \
        mma16(C1, A1h, BH[0], BH[1]);                       \
        mma16((C0) + 4, A0h, BH[2], BH[3]);                 \
        mma16((C1) + 4, A1h, BH[2], BH[3]);                 \
        mma16(C0, A0h, BL[0], BL[1]);                       \
        mma16(C1, A1h, BL[0], BL[1]);                       \
        mma16((C0) + 4, A0h, BL[2], BL[3]);                 \
        mma16((C1) + 4, A1h, BL[2], BL[3]);                 \
        mma16(C0, A0l, BH[0], BH[1]);                       \
        mma16(C1, A1l, BH[0], BH[1]);                       \
        mma16((C0) + 4, A0l, BH[2], BH[3]);                 \
        mma16((C1) + 4, A1l, BH[2], BH[3]);                 \
    } while (0)

// ---------------------------------------------------------------------------
// prep: elems = 47104 + 16384 + 4096 + 6656 = 74240 = 290 * 256
// ---------------------------------------------------------------------------
__global__ void prep_kernel(const float* __restrict__ W1, const float* __restrict__ W2,
                            const float* __restrict__ W3, const float* __restrict__ Whh,
                            const float* __restrict__ Wo) {
    int i = blockIdx.x * 256 + threadIdx.x;
    const int N1 = NCH1 * 256 * 8, N2 = 4 * 128 * 32, N3 = 64 * 64, N4 = 208 * 32;
    if (i < N1) {
        int kc = i >> 11, rem = i & 2047, n = rem >> 3, u = rem & 7;
        int k = kc * 16 + 2 * u;
        float v0 = (k < 361)     ? W1[n * 361 + k]     : 0.f;
        float v1 = (k + 1 < 361) ? W1[n * 361 + k + 1] : 0.f;
        split2(v0, v1, g_W1h[i], g_W1l[i]);
    } else if (i < N1 + N2) {
        int j = i - N1;
        int kc = j >> 12, rem = j & 4095, n = rem >> 5, u = rem & 31;
        int k = kc * 64 + 2 * u;
        split2(W2[n * 256 + k], W2[n * 256 + k + 1], g_W2h[j], g_W2l[j]);
    } else if (i < N1 + N2 + N3) {
        int j = i - N1 - N2;
        int n = j >> 6, u = j & 63;
        split2(W3[n * 128 + 2 * u], W3[n * 128 + 2 * u + 1], g_W3h[j], g_W3l[j]);
    } else if (i < N1 + N2 + N3 + N4) {
        int j = i - N1 - N2 - N3;
        int nn = j >> 5, u = j & 31, k = 2 * u;
        unsigned hi = 0, lo = 0;
        if (nn < 192) {
            int wnx = nn / 48, l = nn % 48, gate = l >> 4, jj = l & 15;
            int orig = gate * 64 + wnx * 16 + jj;
            split2(Whh[orig * 64 + k], Whh[orig * 64 + k + 1], hi, lo);
        } else if (nn < 194) {
            int o = nn - 192;
            split2(Wo[o * 64 + k], Wo[o * 64 + k + 1], hi, lo);
        }
        g_Whh[j] = hi; g_Whl[j] = lo;
    }
}

// ---------------------------------------------------------------------------
// fused kernel: 64 rows/CTA, 256 threads (8 warps = 2m x 4n), 2 CTAs/SM.
// smem (u32 units), peak 26112 = 104448 B:
//  h1hi [64][132] @0, h1lo @8448                              (..16896)
//  P1: zbuf 2x(hi768+lo768) @16896, w1h @19968, w1l @23040    (..26112)
//  P2: w2h [128][36] @16896, w2l @21504                       (..26112)
//  P3: h2hi [64][68] @0, h2lo @4352; w3h [64][68] @16896, w3l @21248
//  GRU: whhh [208][36] @0, whhl @7488, hhi [64][36] @14976, hlo @17280,
//       wih @19584, sbrz @19968, sbin @20096, sbhn @20160, swo @20224,
//       sbo @20352, x @20356, xh [64][20] @20484              (..21764)
// ---------------------------------------------------------------------------
__global__ void __launch_bounds__(256, 2) fused_kernel(
    const float* __restrict__ z,
    const float* __restrict__ b1, const float* __restrict__ b2, const float* __restrict__ b3,
    const float* __restrict__ Wih, const float* __restrict__ bih, const float* __restrict__ bhh,
    const float* __restrict__ Wo, const float* __restrict__ bo,
    float* __restrict__ out)
{
    extern __shared__ float sm[];
    unsigned* smu = (unsigned*)sm;
    const unsigned sb = (unsigned)__cvta_generic_to_shared(sm);

    const int tid = threadIdx.x, lane = tid & 31, wid = tid >> 5;
    const int g = lane >> 2, tg = lane & 3;
    const int wm = wid & 1, wn = wid >> 1;
    const int m0 = blockIdx.x * 64;

    const int arow = lane & 15;
    const int ak4  = (lane >> 4) * 4;
    const int brow = ((lane >> 4) << 3) + (lane & 7);
    const int bk4  = ((lane >> 3) & 1) * 4;

    unsigned* h1hi = smu;            // [64][132]
    unsigned* h1lo = smu + 8448;

    // ================= GEMM1: h1 = relu(z @ W1^T + b1) =================
    float acc1[2][8][4];
    #pragma unroll
    for (int a = 0; a < 2; a++)
        #pragma unroll
        for (int b = 0; b < 8; b++)
            #pragma unroll
            for (int c = 0; c < 4; c++) acc1[a][b][c] = 0.f;

    // z staging: LDG fp32 (prefetched 1 chunk ahead) -> split2 -> packed STS
    auto ldgz = [&](float* v, int kc) {
        int k0 = kc * 16 + (tid & 3) * 4;
        const float* src = z + (size_t)(m0 + (tid >> 2)) * 361 + k0;
        #pragma unroll
        for (int j = 0; j < 4; j++) v[j] = (k0 + j < 361) ? __ldg(src + j) : 0.f;
    };
    auto stsz = [&](int buf, const float* v) {
        unsigned h0, l0, h1, l1;
        split2(v[0], v[1], h0, l0);
        split2(v[2], v[3], h1, l1);
        unsigned* dst = smu + 16896 + buf * 1536 + (tid >> 2) * 12 + (tid & 3) * 2;
        *(uint2*)dst = make_uint2(h0, h1);
        *(uint2*)(dst + 768) = make_uint2(l0, l1);
    };
    auto stage_w1 = [&](int kc) {        // single-buffered W1
        #pragma unroll
        for (int v = 0; v < 2; v++) {
            cpa16(smu + 19968 + tid * 12 + v * 4, g_W1h + kc * 2048 + tid * 8 + v * 4);
            cpa16(smu + 23040 + tid * 12 + v * 4, g_W1l + kc * 2048 + tid * 8 + v * 4);
        }
    };

    const int w1_frag = (wn * 64 + brow) * 12 + bk4;
    const int z_fragA = (wm * 32 + arow) * 12 + ak4;

    float zv[4];
    ldgz(zv, 0);
    for (int kc = 0; kc < NCH1; kc++) {
        stage_w1(kc);                   // safe: prior mma reads done (trailing sync)
        stsz(kc & 1, zv);
        cp_commit();
        if (kc + 1 < NCH1) ldgz(zv, kc + 1);
        cp_wait<0>();
        __syncthreads();
        unsigned a_addr  = sb + 4u * (16896 + (kc & 1) * 1536 + z_fragA);
        unsigned bh_addr = sb + 4u * (19968 + w1_frag);
        unsigned Ah[2][4], Al[2][4];
        ldsm4(Ah[0][0], Ah[0][1], Ah[0][2], Ah[0][3], a_addr);
        ldsm4(Ah[1][0], Ah[1][1], Ah[1][2], Ah[1][3], a_addr + 4u * 192);
        ldsm4(Al[0][0], Al[0][1], Al[0][2], Al[0][3], a_addr + 4u * 768);
        ldsm4(Al[1][0], Al[1][1], Al[1][2], Al[1][3], a_addr + 4u * (768 + 192));
        #pragma unroll
        for (int p = 0; p < 4; p++) {
            unsigned bh[4], bl[4];
            ldsm4(bh[0], bh[1], bh[2], bh[3], bh_addr + 4u * (p * 16 * 12));
            ldsm4(bl[0], bl[1], bl[2], bl[3], bh_addr + 4u * (3072 + p * 16 * 12));
            MMA12(Ah[0], Ah[1], Al[0], Al[1], bh, bl, acc1[0][2*p], acc1[1][2*p]);
        }
        __syncthreads();
    }

    // GEMM1 epilogue -> packed h1
    #pragma unroll
    for (int nt = 0; nt < 8; nt++) {
        #pragma unroll
        for (int mt = 0; mt < 2; mt++) {
            int m = wm * 32 + mt * 16 + g;
            int n = wn * 64 + nt * 8 + 2 * tg;
            int nu = n >> 1;
            float bv0 = __ldg(b1 + n), bv1 = __ldg(b1 + n + 1);
            unsigned hi, lo;
            split2(relu_(acc1[mt][nt][0] + bv0), relu_(acc1[mt][nt][1] + bv1), hi, lo);
            h1hi[m * 132 + nu] = hi; h1lo[m * 132 + nu] = lo;
            split2(relu_(acc1[mt][nt][2] + bv0), relu_(acc1[mt][nt][3] + bv1), hi, lo);
            h1hi[(m + 8) * 132 + nu] = hi; h1lo[(m + 8) * 132 + nu] = lo;
        }
    }

    // ================= GEMM2: single-buffered W2 @16896/21504 =================
    float acc2[2][4][4];
    #pragma unroll
    for (int a = 0; a < 2; a++)
        #pragma unroll
        for (int b = 0; b < 4; b++)
            #pragma unroll
            for (int c = 0; c < 4; c++) acc2[a][b][c] = 0.f;

    const int h1_fragA = (wm * 32 + arow) * 132 + ak4;
    const int w2_fragB = 16896 + (wn * 32 + brow) * 36 + bk4;

    for (int kc = 0; kc < 4; kc++) {
        #pragma unroll
        for (int i = tid; i < 2048; i += 256) {
            int half = i >> 10, j = i & 1023;
            int n = j >> 3, q4 = (j & 7) * 4;
            cpa16(smu + (half ? 21504 : 16896) + n * 36 + q4,
                  (half ? g_W2l : g_W2h) + kc * 4096 + n * 32 + q4);
        }
        cp_commit(); cp_wait<0>();
        __syncthreads();
        #pragma unroll
        for (int q = 0; q < 4; q++) {
            int u0 = kc * 32 + q * 8;
            unsigned Ah[2][4], Al[2][4];
            ldsm4(Ah[0][0], Ah[0][1], Ah[0][2], Ah[0][3], sb + 4u * (h1_fragA + u0));
            ldsm4(Ah[1][0], Ah[1][1], Ah[1][2], Ah[1][3], sb + 4u * (h1_fragA + 16 * 132 + u0));
            ldsm4(Al[0][0], Al[0][1], Al[0][2], Al[0][3], sb + 4u * (8448 + h1_fragA + u0));
            ldsm4(Al[1][0], Al[1][1], Al[1][2], Al[1][3], sb + 4u * (8448 + h1_fragA + 16 * 132 + u0));
            #pragma unroll
            for (int p = 0; p < 2; p++) {
                unsigned bh[4], bl[4];
                ldsm4(bh[0], bh[1], bh[2], bh[3], sb + 4u * (w2_fragB + p * 16 * 36 + q * 8));
                ldsm4(bl[0], bl[1], bl[2], bl[3], sb + 4u * (4608 + w2_fragB + p * 16 * 36 + q * 8));
                MMA12(Ah[0], Ah[1], Al[0], Al[1], bh, bl, acc2[0][2*p], acc2[1][2*p]);
            }
        }
        __syncthreads();
    }

    // ---- stage W3 @16896/21248 (over dead w2) + h2 epilogue @0 (over dead h1) ----
    #pragma unroll
    for (int i = tid; i < 2048; i += 256) {
        int half = i >> 10, j = i & 1023;
        int n = j >> 4, q4 = (j & 15) * 4;
        cpa16(smu + (half ? 21248 : 16896) + n * 68 + q4,
              (half ? g_W3l : g_W3h) + n * 64 + q4);
    }
    cp_commit();

    unsigned* h2hi = smu;          // [64][68]
    unsigned* h2lo = smu + 4352;
    #pragma unroll
    for (int nt = 0; nt < 4; nt++) {
        #pragma unroll
        for (int mt = 0; mt < 2; mt++) {
            int m = wm * 32 + mt * 16 + g;
            int n = wn * 32 + nt * 8 + 2 * tg;
            int nu = n >> 1;
            float bv0 = __ldg(b2 + n), bv1 = __ldg(b2 + n + 1);
            unsigned hi, lo;
            split2(relu_(acc2[mt][nt][0] + bv0), relu_(acc2[mt][nt][1] + bv1), hi, lo);
            h2hi[m * 68 + nu] = hi; h2lo[m * 68 + nu] = lo;
            split2(relu_(acc2[mt][nt][2] + bv0), relu_(acc2[mt][nt][3] + bv1), hi, lo);
            h2hi[(m + 8) * 68 + nu] = hi; h2lo[(m + 8) * 68 + nu] = lo;
        }
    }
    cp_wait<0>();
    __syncthreads();

    // ================= GEMM3 =================
    float acc3[2][2][4];
    #pragma unroll
    for (int a = 0; a < 2; a++)
        #pragma unroll
        for (int b = 0; b < 2; b++)
            #pragma unroll
            for (int c = 0; c < 4; c++) acc3[a][b][c] = 0.f;

    const int h2_fragA = (wm * 32 + arow) * 68 + ak4;
    const int w3_fragB = 16896 + (wn * 16 + brow) * 68 + bk4;

    #pragma unroll
    for (int q = 0; q < 8; q++) {
        int u0 = q * 8;
        unsigned Ah[2][4], Al[2][4];
        ldsm4(Ah[0][0], Ah[0][1], Ah[0][2], Ah[0][3], sb + 4u * (h2_fragA + u0));
        ldsm4(Ah[1][0], Ah[1][1], Ah[1][2], Ah[1][3], sb + 4u * (h2_fragA + 16 * 68 + u0));
        ldsm4(Al[0][0], Al[0][1], Al[0][2], Al[0][3], sb + 4u * (4352 + h2_fragA + u0));
        ldsm4(Al[1][0], Al[1][1], Al[1][2], Al[1][3], sb + 4u * (4352 + h2_fragA + 16 * 68 + u0));
        unsigned bh[4], bl[4];
        ldsm4(bh[0], bh[1], bh[2], bh[3], sb + 4u * (w3_fragB + u0));
        ldsm4(bl[0], bl[1], bl[2], bl[3], sb + 4u * (4352 + w3_fragB + u0));
        MMA12(Ah[0], Ah[1], Al[0], Al[1], bh, bl, acc3[0][0], acc3[1][0]);
    }
    __syncthreads();   // all w3/h2 reads done before overwrite

    // ================= GRU setup =================
    unsigned* whhh = smu;            // [208][36]
    unsigned* whhl = smu + 7488;
    unsigned* hhi  = smu + 14976;    // [64][36]
    unsigned* hlo  = smu + 17280;
    float*    wih  = sm + 19584;     // [192][2]
    float*    sbrz = sm + 19968;     // [128]
    float*    sbin = sm + 20096;     // [64]
    float*    sbhn = sm + 20160;     // [64]
    float*    swo  = sm + 20224;     // [128]
    float*    sbo  = sm + 20352;     // [2]
    float*    x    = sm + 20356;     // [64][2]
    float*    xh   = sm + 20484;     // [64][20]

    #pragma unroll
    for (int i = tid; i < 3328; i += 256) {
        int half = (i >= 1664), j = half ? i - 1664 : i;
        int n = j >> 3, q4 = (j & 7) * 4;
        cpa16((half ? whhl : whhh) + n * 36 + q4, (half ? g_Whl : g_Whh) + n * 32 + q4);
    }
    cp_commit();
    #pragma unroll
    for (int i = tid; i < 384; i += 256) wih[i] = Wih[i];
    if (tid < 128) { sbrz[tid] = bih[tid] + bhh[tid]; swo[tid] = Wo[tid]; x[tid] = 0.f; }
    if (tid >= 128 && tid < 192) { sbin[tid - 128] = bih[tid]; sbhn[tid - 128] = bhh[tid]; }
    if (tid >= 192 && tid < 194) sbo[tid - 192] = bo[tid - 192];

    // GEMM3 epilogue -> packed h @14976 (dead region)
    #pragma unroll
    for (int nt = 0; nt < 2; nt++) {
        #pragma unroll
        for (int mt = 0; mt < 2; mt++) {
            int m = wm * 32 + mt * 16 + g;
            int n = wn * 16 + nt * 8 + 2 * tg;
            int nu = n >> 1;
            float bv0 = __ldg(b3 + n), bv1 = __ldg(b3 + n + 1);
            unsigned hi, lo;
            split2(relu_(acc3[mt][nt][0] + bv0), relu_(acc3[mt][nt][1] + bv1), hi, lo);
            hhi[m * 36 + nu] = hi; hlo[m * 36 + nu] = lo;
            split2(relu_(acc3[mt][nt][2] + bv0), relu_(acc3[mt][nt][3] + bv1), hi, lo);
            hhi[(m + 8) * 36 + nu] = hi; hlo[(m + 8) * 36 + nu] = lo;
        }
    }
    cp_wait<0>();
    __syncthreads();

    // ================= GRU loop: in-register gates =================
    const int h_fragA   = 14976 + (wm * 32 + arow) * 36 + ak4;
    const int whh_fragB = (wn * 48 + brow) * 36 + bk4;
    const int dx_fragB  = (192 + brow) * 36 + bk4;
    const float4* wih4  = (const float4*)wih;
    const float2* sbrz2 = (const float2*)sbrz;
    const float2* sbin2 = (const float2*)sbin;
    const float2* sbhn2 = (const float2*)sbhn;

    for (int t = 0; t < PLEN; t++) {
        float acc[2][6][4];
        float accD[2][4];
        #pragma unroll
        for (int a = 0; a < 2; a++) {
            #pragma unroll
            for (int b = 0; b < 6; b++)
                #pragma unroll
                for (int c = 0; c < 4; c++) acc[a][b][c] = 0.f;
            #pragma unroll
            for (int c = 0; c < 4; c++) accD[a][c] = 0.f;
        }

        #pragma unroll
        for (int q = 0; q < 4; q++) {
            unsigned Ah[2][4], Al[2][4];
            ldsm4(Ah[0][0], Ah[0][1], Ah[0][2], Ah[0][3], sb + 4u * (h_fragA + q * 8));
            ldsm4(Ah[1][0], Ah[1][1], Ah[1][2], Ah[1][3], sb + 4u * (h_fragA + 16 * 36 + q * 8));
            ldsm4(Al[0][0], Al[0][1], Al[0][2], Al[0][3], sb + 4u * (2304 + h_fragA + q * 8));
            ldsm4(Al[1][0], Al[1][1], Al[1][2], Al[1][3], sb + 4u * (2304 + h_fragA + 16 * 36 + q * 8));
            #pragma unroll
            for (int p = 0; p < 3; p++) {
                unsigned bh[4], bl[4];
                ldsm4(bh[0], bh[1], bh[2], bh[3], sb + 4u * (whh_fragB + p * 16 * 36 + q * 8));
                ldsm4(bl[0], bl[1], bl[2], bl[3], sb + 4u * (7488 + whh_fragB + p * 16 * 36 + q * 8));
                MMA12(Ah[0], Ah[1], Al[0], Al[1], bh, bl, acc[0][2*p], acc[1][2*p]);
            }
            if (wn == 3) {  // dx tile (Wo rows 192-193; 194-207 zero)
                unsigned dh[4], dl[4];
                ldsm4(dh[0], dh[1], dh[2], dh[3], sb + 4u * (dx_fragB + q * 8));
                ldsm4(dl[0], dl[1], dl[2], dl[3], sb + 4u * (7488 + dx_fragB + q * 8));
                mma16(accD[0], Ah[0], dh[0], dh[1]);
                mma16(accD[1], Ah[1], dh[0], dh[1]);
                mma16(accD[0], Ah[0], dl[0], dl[1]);
                mma16(accD[1], Ah[1], dl[0], dl[1]);
                mma16(accD[0], Al[0], dh[0], dh[1]);
                mma16(accD[1], Al[1], dh[0], dh[1]);
            }
        }
        // x_{t-1} = x_{t-2} + h_{t-1}@Wo + bo  (cols 192,193 held by tg==0 lanes)
        if (t > 0 && wn == 3 && tg == 0) {
            float so0 = sbo[0], so1 = sbo[1];
            #pragma unroll
            for (int mt = 0; mt < 2; mt++) {
                #pragma unroll
                for (int sel = 0; sel < 2; sel++) {
                    int row = wm * 32 + mt * 16 + g + sel * 8;
                    float xv0 = x[2 * row]     + accD[mt][sel * 2]     + so0;
                    float xv1 = x[2 * row + 1] + accD[mt][sel * 2 + 1] + so1;
                    x[2 * row] = xv0; x[2 * row + 1] = xv1;
                    xh[row * 20 + (t - 1) * 2]     = xv0;
                    xh[row * 20 + (t - 1) * 2 + 1] = xv1;
                }
            }
        }
        __syncthreads();

        // gates from registers; h updated in place (thread owns its elements)
        #pragma unroll
        for (int mt = 0; mt < 2; mt++) {
            int r0 = wm * 32 + mt * 16 + g;
            #pragma unroll
            for (int b = 0; b < 2; b++) {
                int q = wn * 8 + b * 4 + tg;
                float4 wr = wih4[q], wz = wih4[32 + q], wnv = wih4[64 + q];
                float2 br = sbrz2[q], bz = sbrz2[32 + q];
                float2 bi = sbin2[q], bh2 = sbhn2[q];
                #pragma unroll
                for (int sel = 0; sel < 2; sel++) {
                    int row = r0 + sel * 8;
                    int ai = sel * 2;
                    float xv0 = x[2 * row], xv1 = x[2 * row + 1];
                    float rg0 = 0.5f * tanhapx(0.5f * (acc[mt][b][ai]     + xv0 * wr.x + xv1 * wr.y + br.x)) + 0.5f;
                    float rg1 = 0.5f * tanhapx(0.5f * (acc[mt][b][ai + 1] + xv0 * wr.z + xv1 * wr.w + br.y)) + 0.5f;
                    float zg0 = 0.5f * tanhapx(0.5f * (acc[mt][2 + b][ai]     + xv0 * wz.x + xv1 * wz.y + bz.x)) + 0.5f;
                    float zg1 = 0.5f * tanhapx(0.5f * (acc[mt][2 + b][ai + 1] + xv0 * wz.z + xv1 * wz.w + bz.y)) + 0.5f;
                    float ng0 = tanhapx(xv0 * wnv.x + xv1 * wnv.y + bi.x + rg0 * (acc[mt][4 + b][ai]     + bh2.x));
                    float ng1 = tanhapx(xv0 * wnv.z + xv1 * wnv.w + bi.y + rg1 * (acc[mt][4 + b][ai + 1] + bh2.y));
                    unsigned uh = hhi[row * 36 + q], ul = hlo[row * 36 + q];
                    float h0 = bflo(uh) + bflo(ul);
                    float h1 = bfhi(uh) + bfhi(ul);
                    float hn0 = (1.f - zg0) * ng0 + zg0 * h0;
                    float hn1 = (1.f - zg1) * ng1 + zg1 * h1;
                    unsigned nh, nl;
                    split2(hn0, hn1, nh, nl);
                    hhi[row * 36 + q] = nh; hlo[row * 36 + q] = nl;
                }
            }
        }
        __syncthreads();
    }

    // final Wo (step PLEN-1)
    if (tid < 128) {
        int r = tid >> 1, o = tid & 1;
        float s = sbo[o];
        const float* wr = swo + o * 64;
        #pragma unroll 8
        for (int c = 0; c < 32; c++) {
            unsigned uh = hhi[r * 36 + c], ul = hlo[r * 36 + c];
            s += (bflo(uh) + bflo(ul)) * wr[2 * c];
            s += (bfhi(uh) + bfhi(ul)) * wr[2 * c + 1];
        }
        float xv = x[r * 2 + o] + s;
        xh[r * 20 + (PLEN - 1) * 2 + o] = xv;
    }
    __syncthreads();

    // coalesced output: out[b, t, o]
    #pragma unroll
    for (int i = tid; i < 320; i += 256) {
        int r = i / 5, q = (i % 5) * 4;
        *(float4*)&out[(size_t)(m0 + r) * 20 + q] = *(const float4*)&xh[r * 20 + q];
    }
}

// ---------------------------------------------------------------------------
extern "C" void kernel_launch(void* const* d_in, const int* in_sizes, int n_in,
                              void* d_out, int out_size)
{
    const float* z   = (const float*)d_in[0];
    const float* W1  = (const float*)d_in[1];
    const float* b1  = (const float*)d_in[2];
    const float* W2  = (const float*)d_in[3];
    const float* b2  = (const float*)d_in[4];
    const float* W3  = (const float*)d_in[5];
    const float* b3  = (const float*)d_in[6];
    const float* Wih = (const float*)d_in[7];
    const float* Whh = (const float*)d_in[8];
    const float* bih = (const float*)d_in[9];
    const float* bhh = (const float*)d_in[10];
    const float* Wo  = (const float*)d_in[11];
    const float* bo  = (const float*)d_in[12];
    float* out = (float*)d_out;

    const int smem = 26112 * 4;  // 104448 B -> 2 CTAs/SM
    cudaFuncSetAttribute(fused_kernel, cudaFuncAttributeMaxDynamicSharedMemorySize, smem);

    prep_kernel<<<290, 256>>>(W1, W2, W3, Whh, Wo);
    fused_kernel<<<BS / 64, 256, smem>>>(z, b1, b2, b3, Wih, bih, bhh, Wo, bo, out);
}

// round 17
// speedup vs baseline: 1.0601x; 1.0601x over previous
#include <cuda_runtime.h>
#include <cuda_bf16.h>

#define BS 131072
#define PLEN 10
#define NCH1 23   // GEMM1: K=361 padded to 368 = 23 chunks of 16

// -------- pre-split weights: packed bf16 (2 per u32 along k), hi & lo, natural order.
// g_Whh holds 208 rows: 0-191 = Whh rows PERMUTED gate-interleaved per 48-row warp
// slice ([r x16 | z x16 | n x16] of the same 16 units), 192-193 = Wo, 194-207 = zero.
__device__ __align__(16) unsigned g_W1h[NCH1 * 256 * 8], g_W1l[NCH1 * 256 * 8]; // [kc][n][8]
__device__ __align__(16) unsigned g_W2h[4 * 128 * 32],   g_W2l[4 * 128 * 32];   // [kc][n][32]
__device__ __align__(16) unsigned g_W3h[64 * 64],        g_W3l[64 * 64];        // [n][64]
__device__ __align__(16) unsigned g_Whh[208 * 32],       g_Whl[208 * 32];       // [n][32]

// ---------------------------------------------------------------------------
__device__ __forceinline__ unsigned packbf(float lo, float hi) {
    unsigned r;
    asm("cvt.rn.bf16x2.f32 %0, %1, %2;" : "=r"(r) : "f"(hi), "f"(lo));
    return r;
}
__device__ __forceinline__ void split2(float v0, float v1, unsigned& hi, unsigned& lo) {
    hi = packbf(v0, v1);
    float h0 = __uint_as_float(hi << 16);
    float h1 = __uint_as_float(hi & 0xffff0000u);
    lo = packbf(v0 - h0, v1 - h1);
}
__device__ __forceinline__ float bflo(unsigned u) { return __uint_as_float(u << 16); }
__device__ __forceinline__ float bfhi(unsigned u) { return __uint_as_float(u & 0xffff0000u); }
__device__ __forceinline__ float relu_(float v) { return v > 0.f ? v : 0.f; }
__device__ __forceinline__ float tanhapx(float x) {
    float y; asm("tanh.approx.f32 %0, %1;" : "=f"(y) : "f"(x)); return y;
}

__device__ __forceinline__ void mma16(float* c, const unsigned* a, unsigned b0, unsigned b1) {
    asm("mma.sync.aligned.m16n8k16.row.col.f32.bf16.bf16.f32 "
        "{%0,%1,%2,%3},{%4,%5,%6,%7},{%8,%9},{%0,%1,%2,%3};"
        : "+f"(c[0]), "+f"(c[1]), "+f"(c[2]), "+f"(c[3])
        : "r"(a[0]), "r"(a[1]), "r"(a[2]), "r"(a[3]), "r"(b0), "r"(b1));
}

__device__ __forceinline__ void ldsm4(unsigned& r0, unsigned& r1, unsigned& r2, unsigned& r3,
                                      unsigned addr) {
    asm volatile("ldmatrix.sync.aligned.m8n8.x4.shared.b16 {%0,%1,%2,%3}, [%4];"
        : "=r"(r0), "=r"(r1), "=r"(r2), "=r"(r3) : "r"(addr));
}

__device__ __forceinline__ void cpa16(void* s, const void* g) {
    unsigned a = (unsigned)__cvta_generic_to_shared(s);
    asm volatile("cp.async.cg.shared.global [%0],[%1],16;" :: "r"(a), "l"(g) : "memory");
}
__device__ __forceinline__ void cp_commit() { asm volatile("cp.async.commit_group;" ::: "memory"); }
template <int N>
__device__ __forceinline__ void cp_wait() { asm volatile("cp.async.wait_group %0;" :: "n"(N) : "memory"); }

// 12-mma group, dependency distance 4; per-acc order (hh, hl, lh) preserved
#define MMA12(A0h, A1h, A0l, A1l, BH, BL, C0, C1)          \
    do {                                                    \
        mma16(C0, A0h, BH[0], BH[1]);                       \
        mma16(C1, A1h, BH[0], BH[1]);                       \
        mma16((C0) + 4, A0h, BH[2], BH[3]);                 \
        mma16((C1) + 4, A1h, BH[2], BH[3]);                 \
        mma16(C0, A0h, BL[0], BL[1]);                       \
        mma16(C1, A1h, BL[0], BL[1]);                       \
        mma16((C0) + 4, A0h, BL[2], BL[3]);                 \
        mma16((C1) + 4, A1h, BL[2], BL[3]);                 \
        mma16(C0, A0l, BH[0], BH[1]);                       \
        mma16(C1, A1l, BH[0], BH[1]);                       \
        mma16((C0) + 4, A0l, BH[2], BH[3]);                 \
        mma16((C1) + 4, A1l, BH[2], BH[3]);                 \
    } while (0)

// ---------------------------------------------------------------------------
// prep: elems = 47104 + 16384 + 4096 + 6656 = 74240 = 290 * 256
// ---------------------------------------------------------------------------
__global__ void prep_kernel(const float* __restrict__ W1, const float* __restrict__ W2,
                            const float* __restrict__ W3, const float* __restrict__ Whh,
                            const float* __restrict__ Wo) {
    int i = blockIdx.x * 256 + threadIdx.x;
    const int N1 = NCH1 * 256 * 8, N2 = 4 * 128 * 32, N3 = 64 * 64, N4 = 208 * 32;
    if (i < N1) {
        int kc = i >> 11, rem = i & 2047, n = rem >> 3, u = rem & 7;
        int k = kc * 16 + 2 * u;
        float v0 = (k < 361)     ? W1[n * 361 + k]     : 0.f;
        float v1 = (k + 1 < 361) ? W1[n * 361 + k + 1] : 0.f;
        split2(v0, v1, g_W1h[i], g_W1l[i]);
    } else if (i < N1 + N2) {
        int j = i - N1;
        int kc = j >> 12, rem = j & 4095, n = rem >> 5, u = rem & 31;
        int k = kc * 64 + 2 * u;
        split2(W2[n * 256 + k], W2[n * 256 + k + 1], g_W2h[j], g_W2l[j]);
    } else if (i < N1 + N2 + N3) {
        int j = i - N1 - N2;
        int n = j >> 6, u = j & 63;
        split2(W3[n * 128 + 2 * u], W3[n * 128 + 2 * u + 1], g_W3h[j], g_W3l[j]);
    } else if (i < N1 + N2 + N3 + N4) {
        int j = i - N1 - N2 - N3;
        int nn = j >> 5, u = j & 31, k = 2 * u;
        unsigned hi = 0, lo = 0;
        if (nn < 192) {
            int wnx = nn / 48, l = nn % 48, gate = l >> 4, jj = l & 15;
            int orig = gate * 64 + wnx * 16 + jj;
            split2(Whh[orig * 64 + k], Whh[orig * 64 + k + 1], hi, lo);
        } else if (nn < 194) {
            int o = nn - 192;
            split2(Wo[o * 64 + k], Wo[o * 64 + k + 1], hi, lo);
        }
        g_Whh[j] = hi; g_Whl[j] = lo;
    }
}

// ---------------------------------------------------------------------------
// fused kernel: 128 rows/CTA, 512 threads (R15 shape) with single-sync
// pipelines in GEMM1/GEMM2 (stage AFTER the top sync; trailing sync removed).
// P1 smem (u32): h1hi [128][132] @0, h1lo @16896;
//   zh 2x[128][12] @33792(+1536), zl @36864(+1536),
//   w1h 2x[256][12] @39936, w1l @46080 (..52224 exactly)
// ---------------------------------------------------------------------------
__global__ void __launch_bounds__(512, 1) fused_kernel(
    const float* __restrict__ z,
    const float* __restrict__ b1, const float* __restrict__ b2, const float* __restrict__ b3,
    const float* __restrict__ Wih, const float* __restrict__ bih, const float* __restrict__ bhh,
    const float* __restrict__ Wo, const float* __restrict__ bo,
    float* __restrict__ out)
{
    extern __shared__ float sm[];
    unsigned* smu = (unsigned*)sm;
    const unsigned sb = (unsigned)__cvta_generic_to_shared(sm);

    const int tid = threadIdx.x, lane = tid & 31, wid = tid >> 5;
    const int g = lane >> 2, tg = lane & 3;
    const int wm = wid & 3, wn = wid >> 2;
    const int m0 = blockIdx.x * 128;

    const int arow = lane & 15;
    const int ak4  = (lane >> 4) * 4;
    const int brow = ((lane >> 4) << 3) + (lane & 7);
    const int bk4  = ((lane >> 3) & 1) * 4;

    unsigned* h1hi = smu;            // [128][132]
    unsigned* h1lo = smu + 16896;

    // ================= GEMM1: h1 = relu(z @ W1^T + b1) =================
    float acc1[2][8][4];
    #pragma unroll
    for (int a = 0; a < 2; a++)
        #pragma unroll
        for (int b = 0; b < 8; b++)
            #pragma unroll
            for (int c = 0; c < 4; c++) acc1[a][b][c] = 0.f;

    // z staging: LDG fp32 (prefetched 1 chunk ahead) -> split2 -> packed STS
    auto ldgz = [&](float* v, int kc) {
        int k0 = kc * 16 + (tid & 3) * 4;
        const float* src = z + (size_t)(m0 + (tid >> 2)) * 361 + k0;
        #pragma unroll
        for (int j = 0; j < 4; j++) v[j] = (k0 + j < 361) ? __ldg(src + j) : 0.f;
    };
    auto stsz = [&](int buf, const float* v) {
        unsigned h0, l0, h1, l1;
        split2(v[0], v[1], h0, l0);
        split2(v[2], v[3], h1, l1);
        unsigned* dst = smu + 33792 + buf * 1536 + (tid >> 2) * 12 + (tid & 3) * 2;
        *(uint2*)dst = make_uint2(h0, h1);
        *(uint2*)(dst + 3072) = make_uint2(l0, l1);
    };
    auto stage_w1 = [&](int buf, int kc) {
        int n = tid >> 1, q4 = (tid & 1) * 4;
        cpa16(smu + 39936 + buf * 3072 + n * 12 + q4, g_W1h + kc * 2048 + n * 8 + q4);
        cpa16(smu + 46080 + buf * 3072 + n * 12 + q4, g_W1l + kc * 2048 + n * 8 + q4);
    };

    const int w1_frag = (wn * 64 + brow) * 12 + bk4;
    const int z_fragA = (wm * 32 + arow) * 12 + ak4;

    float zv[4];
    ldgz(zv, 0); stsz(0, zv);      // chunk 0 staged directly
    stage_w1(0, 0); cp_commit();
    ldgz(zv, 1);                   // prefetch chunk 1

    for (int kc = 0; kc < NCH1; kc++) {
        cp_wait<0>();
        __syncthreads();           // buf kc ready; all warps done with buf kc-1 reads
        if (kc + 1 < NCH1) {
            stsz((kc + 1) & 1, zv);
            stage_w1((kc + 1) & 1, kc + 1); cp_commit();
            if (kc + 2 < NCH1) ldgz(zv, kc + 2);
        }
        unsigned a_addr  = sb + 4u * (33792 + (kc & 1) * 1536 + z_fragA);
        unsigned bh_addr = sb + 4u * (39936 + (kc & 1) * 3072 + w1_frag);
        unsigned Ah[2][4], Al[2][4];
        ldsm4(Ah[0][0], Ah[0][1], Ah[0][2], Ah[0][3], a_addr);
        ldsm4(Ah[1][0], Ah[1][1], Ah[1][2], Ah[1][3], a_addr + 4u * 192);
        ldsm4(Al[0][0], Al[0][1], Al[0][2], Al[0][3], a_addr + 4u * 3072);
        ldsm4(Al[1][0], Al[1][1], Al[1][2], Al[1][3], a_addr + 4u * (3072 + 192));
        #pragma unroll
        for (int p = 0; p < 4; p++) {
            unsigned bh[4], bl[4];
            ldsm4(bh[0], bh[1], bh[2], bh[3], bh_addr + 4u * (p * 16 * 12));
            ldsm4(bl[0], bl[1], bl[2], bl[3], bh_addr + 4u * (6144 + p * 16 * 12));
            MMA12(Ah[0], Ah[1], Al[0], Al[1], bh, bl, acc1[0][2*p], acc1[1][2*p]);
        }
    }
    __syncthreads();   // all GEMM1 reads done before W2 prefetch overwrites region

    // prefetch W2 chunk 0
    auto stage2 = [&](int buf, int kc) {
        #pragma unroll
        for (int i = tid; i < 1024; i += 512) {
            int n = i >> 3, q4 = (i & 7) * 4;
            cpa16(smu + 33792 + buf * 4608 + n * 36 + q4, g_W2h + kc * 4096 + n * 32 + q4);
            cpa16(smu + 43008 + buf * 4608 + n * 36 + q4, g_W2l + kc * 4096 + n * 32 + q4);
        }
    };
    stage2(0, 0); cp_commit();

    // GEMM1 epilogue -> packed h1
    #pragma unroll
    for (int mt = 0; mt < 2; mt++) {
        #pragma unroll
        for (int nt = 0; nt < 8; nt++) {
            int m = wm * 32 + mt * 16 + g;
            int n = wn * 64 + nt * 8 + 2 * tg;
            int nu = n >> 1;
            float bv0 = __ldg(b1 + n), bv1 = __ldg(b1 + n + 1);
            unsigned hi, lo;
            split2(relu_(acc1[mt][nt][0] + bv0), relu_(acc1[mt][nt][1] + bv1), hi, lo);
            h1hi[m * 132 + nu] = hi; h1lo[m * 132 + nu] = lo;
            split2(relu_(acc1[mt][nt][2] + bv0), relu_(acc1[mt][nt][3] + bv1), hi, lo);
            h1hi[(m + 8) * 132 + nu] = hi; h1lo[(m + 8) * 132 + nu] = lo;
        }
    }
    __syncthreads();

    // ================= GEMM2 (single-sync pipeline) =================
    float acc2[2][4][4];
    #pragma unroll
    for (int a = 0; a < 2; a++)
        #pragma unroll
        for (int b = 0; b < 4; b++)
            #pragma unroll
            for (int c = 0; c < 4; c++) acc2[a][b][c] = 0.f;

    const int h1_fragA = (wm * 32 + arow) * 132 + ak4;
    const int w2_fragB = (wn * 32 + brow) * 36 + bk4;

    for (int kc = 0; kc < 4; kc++) {
        cp_wait<0>();
        __syncthreads();
        if (kc + 1 < 4) { stage2((kc + 1) & 1, kc + 1); cp_commit(); }
        unsigned w2h_addr = sb + 4u * (33792 + (kc & 1) * 4608 + w2_fragB);
        unsigned w2l_addr = w2h_addr + 4u * 9216;
        #pragma unroll
        for (int q = 0; q < 4; q++) {
            int u0 = kc * 32 + q * 8;
            unsigned Ah[2][4], Al[2][4];
            ldsm4(Ah[0][0], Ah[0][1], Ah[0][2], Ah[0][3], sb + 4u * (h1_fragA + u0));
            ldsm4(Ah[1][0], Ah[1][1], Ah[1][2], Ah[1][3], sb + 4u * (h1_fragA + 16 * 132 + u0));
            ldsm4(Al[0][0], Al[0][1], Al[0][2], Al[0][3], sb + 4u * (16896 + h1_fragA + u0));
            ldsm4(Al[1][0], Al[1][1], Al[1][2], Al[1][3], sb + 4u * (16896 + h1_fragA + 16 * 132 + u0));
            #pragma unroll
            for (int p = 0; p < 2; p++) {
                unsigned bh[4], bl[4];
                ldsm4(bh[0], bh[1], bh[2], bh[3], w2h_addr + 4u * (p * 16 * 36 + q * 8));
                ldsm4(bl[0], bl[1], bl[2], bl[3], w2l_addr + 4u * (p * 16 * 36 + q * 8));
                MMA12(Ah[0], Ah[1], Al[0], Al[1], bh, bl, acc2[0][2*p], acc2[1][2*p]);
            }
        }
    }
    __syncthreads();   // all GEMM2 reads (h1 + w2) done before region reuse

    // ---- stage W3 @8704/13056 + h2 epilogue @33792 ----
    unsigned* w3h = smu + 8704;   // [64][68]
    unsigned* w3l = smu + 13056;
    #pragma unroll
    for (int i = tid; i < 2048; i += 512) {
        int half = i >> 10, j = i & 1023;
        int n = j >> 4, q4 = (j & 15) * 4;
        cpa16((half ? w3l : w3h) + n * 68 + q4, (half ? g_W3l : g_W3h) + n * 64 + q4);
    }
    cp_commit();

    unsigned* h2hi = smu + 33792;  // [128][68]
    unsigned* h2lo = smu + 42496;
    #pragma unroll
    for (int mt = 0; mt < 2; mt++) {
        #pragma unroll
        for (int nt = 0; nt < 4; nt++) {
            int m = wm * 32 + mt * 16 + g;
            int n = wn * 32 + nt * 8 + 2 * tg;
            int nu = n >> 1;
            float bv0 = __ldg(b2 + n), bv1 = __ldg(b2 + n + 1);
            unsigned hi, lo;
            split2(relu_(acc2[mt][nt][0] + bv0), relu_(acc2[mt][nt][1] + bv1), hi, lo);
            h2hi[m * 68 + nu] = hi; h2lo[m * 68 + nu] = lo;
            split2(relu_(acc2[mt][nt][2] + bv0), relu_(acc2[mt][nt][3] + bv1), hi, lo);
            h2hi[(m + 8) * 68 + nu] = hi; h2lo[(m + 8) * 68 + nu] = lo;
        }
    }
    cp_wait<0>();
    __syncthreads();

    // ================= GEMM3 =================
    float acc3[2][2][4];
    #pragma unroll
    for (int a = 0; a < 2; a++)
        #pragma unroll
        for (int b = 0; b < 2; b++)
            #pragma unroll
            for (int c = 0; c < 4; c++) acc3[a][b][c] = 0.f;

    const int h2_fragA = 33792 + (wm * 32 + arow) * 68 + ak4;
    const int w3_fragB = 8704 + (wn * 16 + brow) * 68 + bk4;

    #pragma unroll
    for (int q = 0; q < 8; q++) {
        int u0 = q * 8;
        unsigned Ah[2][4], Al[2][4];
        ldsm4(Ah[0][0], Ah[0][1], Ah[0][2], Ah[0][3], sb + 4u * (h2_fragA + u0));
        ldsm4(Ah[1][0], Ah[1][1], Ah[1][2], Ah[1][3], sb + 4u * (h2_fragA + 16 * 68 + u0));
        ldsm4(Al[0][0], Al[0][1], Al[0][2], Al[0][3], sb + 4u * (8704 + h2_fragA + u0));
        ldsm4(Al[1][0], Al[1][1], Al[1][2], Al[1][3], sb + 4u * (8704 + h2_fragA + 16 * 68 + u0));
        unsigned bh[4], bl[4];
        ldsm4(bh[0], bh[1], bh[2], bh[3], sb + 4u * (w3_fragB + u0));
        ldsm4(bl[0], bl[1], bl[2], bl[3], sb + 4u * (4352 + w3_fragB + u0));
        MMA12(Ah[0], Ah[1], Al[0], Al[1], bh, bl, acc3[0][0], acc3[1][0]);
    }
    __syncthreads();   // all w3/h2 reads done before overwrite

    // ================= GRU setup =================
    unsigned* hhi  = smu;            // [128][36]
    unsigned* hlo  = smu + 4608;
    unsigned* whhh = smu + 9216;     // [208][36]
    unsigned* whhl = smu + 16704;
    float*    wih  = sm + 24192;     // [192][2]
    float*    sbrz = sm + 24576;     // [128]
    float*    sbin = sm + 24704;     // [64]
    float*    sbhn = sm + 24768;     // [64]
    float*    swo  = sm + 24832;     // [128]
    float*    sbo  = sm + 24960;     // [2]
    float*    x    = sm + 24964;     // [128][2]
    float*    xh   = sm + 25220;     // [128][20]

    #pragma unroll
    for (int i = tid; i < 3328; i += 512) {
        int half = (i >= 1664), j = half ? i - 1664 : i;
        int n = j >> 3, q4 = (j & 7) * 4;
        cpa16((half ? whhl : whhh) + n * 36 + q4, (half ? g_Whl : g_Whh) + n * 32 + q4);
    }
    cp_commit();
    if (tid < 384) wih[tid] = Wih[tid];
    if (tid < 128) sbrz[tid] = bih[tid] + bhh[tid];
    if (tid >= 128 && tid < 192) { sbin[tid - 128] = bih[tid]; sbhn[tid - 128] = bhh[tid]; }
    if (tid >= 192 && tid < 320) swo[tid - 192] = Wo[tid - 192];
    if (tid >= 320 && tid < 322) sbo[tid - 320] = bo[tid - 320];
    if (tid < 256) x[tid] = 0.f;

    // GEMM3 epilogue -> packed h
    #pragma unroll
    for (int mt = 0; mt < 2; mt++) {
        #pragma unroll
        for (int nt = 0; nt < 2; nt++) {
            int m = wm * 32 + mt * 16 + g;
            int n = wn * 16 + nt * 8 + 2 * tg;
            int nu = n >> 1;
            float bv0 = __ldg(b3 + n), bv1 = __ldg(b3 + n + 1);
            unsigned hi, lo;
            split2(relu_(acc3[mt][nt][0] + bv0), relu_(acc3[mt][nt][1] + bv1), hi, lo);
            hhi[m * 36 + nu] = hi; hlo[m * 36 + nu] = lo;
            split2(relu_(acc3[mt][nt][2] + bv0), relu_(acc3[mt][nt][3] + bv1), hi, lo);
            hhi[(m + 8) * 36 + nu] = hi; hlo[(m + 8) * 36 + nu] = lo;
        }
    }
    cp_wait<0>();
    __syncthreads();

    // ================= GRU loop: in-register gates =================
    const int h_fragA   = (wm * 32 + arow) * 36 + ak4;
    const int whh_fragB = 9216 + (wn * 48 + brow) * 36 + bk4;
    const int dx_fragB  = 9216 + (192 + brow) * 36 + bk4;
    const float4* wih4  = (const float4*)wih;
    const float2* sbrz2 = (const float2*)sbrz;
    const float2* sbin2 = (const float2*)sbin;
    const float2* sbhn2 = (const float2*)sbhn;

    for (int t = 0; t < PLEN; t++) {
        float acc[2][6][4];
        float accD[2][4];
        #pragma unroll
        for (int a = 0; a < 2; a++) {
            #pragma unroll
            for (int b = 0; b < 6; b++)
                #pragma unroll
                for (int c = 0; c < 4; c++) acc[a][b][c] = 0.f;
            #pragma unroll
            for (int c = 0; c < 4; c++) accD[a][c] = 0.f;
        }

        #pragma unroll
        for (int q = 0; q < 4; q++) {
            unsigned Ah[2][4], Al[2][4];
            ldsm4(Ah[0][0], Ah[0][1], Ah[0][2], Ah[0][3], sb + 4u * (h_fragA + q * 8));
            ldsm4(Ah[1][0], Ah[1][1], Ah[1][2], Ah[1][3], sb + 4u * (h_fragA + 16 * 36 + q * 8));
            ldsm4(Al[0][0], Al[0][1], Al[0][2], Al[0][3], sb + 4u * (4608 + h_fragA + q * 8));
            ldsm4(Al[1][0], Al[1][1], Al[1][2], Al[1][3], sb + 4u * (4608 + h_fragA + 16 * 36 + q * 8));
            #pragma unroll
            for (int p = 0; p < 3; p++) {
                unsigned bh[4], bl[4];
                ldsm4(bh[0], bh[1], bh[2], bh[3], sb + 4u * (whh_fragB + p * 16 * 36 + q * 8));
                ldsm4(bl[0], bl[1], bl[2], bl[3], sb + 4u * (7488 + whh_fragB + p * 16 * 36 + q * 8));
                MMA12(Ah[0], Ah[1], Al[0], Al[1], bh, bl, acc[0][2*p], acc[1][2*p]);
            }
            if (wn == 3) {  // dx tile (Wo rows 192-193; 194-207 zero)
                unsigned dh[4], dl[4];
                ldsm4(dh[0], dh[1], dh[2], dh[3], sb + 4u * (dx_fragB + q * 8));
                ldsm4(dl[0], dl[1], dl[2], dl[3], sb + 4u * (7488 + dx_fragB + q * 8));
                mma16(accD[0], Ah[0], dh[0], dh[1]);
                mma16(accD[1], Ah[1], dh[0], dh[1]);
                mma16(accD[0], Ah[0], dl[0], dl[1]);
                mma16(accD[1], Ah[1], dl[0], dl[1]);
                mma16(accD[0], Al[0], dh[0], dh[1]);
                mma16(accD[1], Al[1], dh[0], dh[1]);
            }
        }
        // x_{t-1} = x_{t-2} + h_{t-1}@Wo + bo  (cols 192,193 held by tg==0 lanes)
        if (t > 0 && wn == 3 && tg == 0) {
            float so0 = sbo[0], so1 = sbo[1];
            #pragma unroll
            for (int mt = 0; mt < 2; mt++) {
                #pragma unroll
                for (int sel = 0; sel < 2; sel++) {
                    int row = wm * 32 + mt * 16 + g + sel * 8;
                    float xv0 = x[2 * row]     + accD[mt][sel * 2]     + so0;
                    float xv1 = x[2 * row + 1] + accD[mt][sel * 2 + 1] + so1;
                    x[2 * row] = xv0; x[2 * row + 1] = xv1;
                    xh[row * 20 + (t - 1) * 2]     = xv0;
                    xh[row * 20 + (t - 1) * 2 + 1] = xv1;
                }
            }
        }
        __syncthreads();

        // gates from registers; h updated in place (thread owns its elements)
        #pragma unroll
        for (int mt = 0; mt < 2; mt++) {
            int r0 = wm * 32 + mt * 16 + g;
            #pragma unroll
            for (int b = 0; b < 2; b++) {
                int q = wn * 8 + b * 4 + tg;
                float4 wr = wih4[q], wz = wih4[32 + q], wnv = wih4[64 + q];
                float2 br = sbrz2[q], bz = sbrz2[32 + q];
                float2 bi = sbin2[q], bh2 = sbhn2[q];
                #pragma unroll
                for (int sel = 0; sel < 2; sel++) {
                    int row = r0 + sel * 8;
                    int ai = sel * 2;
                    float xv0 = x[2 * row], xv1 = x[2 * row + 1];
                    float rg0 = 0.5f * tanhapx(0.5f * (acc[mt][b][ai]     + xv0 * wr.x + xv1 * wr.y + br.x)) + 0.5f;
                    float rg1 = 0.5f * tanhapx(0.5f * (acc[mt][b][ai + 1] + xv0 * wr.z + xv1 * wr.w + br.y)) + 0.5f;
                    float zg0 = 0.5f * tanhapx(0.5f * (acc[mt][2 + b][ai]     + xv0 * wz.x + xv1 * wz.y + bz.x)) + 0.5f;
                    float zg1 = 0.5f * tanhapx(0.5f * (acc[mt][2 + b][ai + 1] + xv0 * wz.z + xv1 * wz.w + bz.y)) + 0.5f;
                    float ng0 = tanhapx(xv0 * wnv.x + xv1 * wnv.y + bi.x + rg0 * (acc[mt][4 + b][ai]     + bh2.x));
                    float ng1 = tanhapx(xv0 * wnv.z + xv1 * wnv.w + bi.y + rg1 * (acc[mt][4 + b][ai + 1] + bh2.y));
                    unsigned uh = hhi[row * 36 + q], ul = hlo[row * 36 + q];
                    float h0 = bflo(uh) + bflo(ul);
                    float h1 = bfhi(uh) + bfhi(ul);
                    float hn0 = (1.f - zg0) * ng0 + zg0 * h0;
                    float hn1 = (1.f - zg1) * ng1 + zg1 * h1;
                    unsigned nh, nl;
                    split2(hn0, hn1, nh, nl);
                    hhi[row * 36 + q] = nh; hlo[row * 36 + q] = nl;
                }
            }
        }
        __syncthreads();
    }

    // final Wo (step PLEN-1)
    if (tid < 256) {
        int r = tid >> 1, o = tid & 1;
        float s = sbo[o];
        const float* wr = swo + o * 64;
        #pragma unroll 8
        for (int c = 0; c < 32; c++) {
            unsigned uh = hhi[r * 36 + c], ul = hlo[r * 36 + c];
            s += (bflo(uh) + bflo(ul)) * wr[2 * c];
            s += (bfhi(uh) + bfhi(ul)) * wr[2 * c + 1];
        }
        float xv = x[r * 2 + o] + s;
        xh[r * 20 + (PLEN - 1) * 2 + o] = xv;
    }
    __syncthreads();

    // coalesced output: out[b, t, o]
    #pragma unroll
    for (int i = tid; i < 640; i += 512) {
        int r = i / 5, q = (i % 5) * 4;
        *(float4*)&out[(size_t)(m0 + r) * 20 + q] = *(const float4*)&xh[r * 20 + q];
    }
}

// ---------------------------------------------------------------------------
extern "C" void kernel_launch(void* const* d_in, const int* in_sizes, int n_in,
                              void* d_out, int out_size)
{
    const float* z   = (const float*)d_in[0];
    const float* W1  = (const float*)d_in[1];
    const float* b1  = (const float*)d_in[2];
    const float* W2  = (const float*)d_in[3];
    const float* b2  = (const float*)d_in[4];
    const float* W3  = (const float*)d_in[5];
    const float* b3  = (const float*)d_in[6];
    const float* Wih = (const float*)d_in[7];
    const float* Whh = (const float*)d_in[8];
    const float* bih = (const float*)d_in[9];
    const float* bhh = (const float*)d_in[10];
    const float* Wo  = (const float*)d_in[11];
    const float* bo  = (const float*)d_in[12];
    float* out = (float*)d_out;

    const int smem = 52224 * 4;  // 208896 B
    cudaFuncSetAttribute(fused_kernel, cudaFuncAttributeMaxDynamicSharedMemorySize, smem);

    prep_kernel<<<290, 256>>>(W1, W2, W3, Whh, Wo);
    fused_kernel<<<BS / 128, 512, smem>>>(z, b1, b2, b3, Wih, bih, bhh, Wo, bo, out);
}